// round 1
// baseline (speedup 1.0000x reference)
#include <cuda_runtime.h>
#include <cuda_bf16.h>
#include <cstdint>

#define NUM_USERS 50000
#define NUM_ITEMS 40000
#define EMB 64
#define NNZ 2000000
#define BATCH 1024
#define INTMX 0x7FFFFFFF

// ---- scratch (static __device__ globals; no allocation allowed) ----
__device__ float         g_WqT[NUM_ITEMS * 128];     // Wq transposed: [item][128]
__device__ __nv_bfloat16 g_Wpb[NUM_ITEMS * EMB];     // Wp in bf16:   [item][64]
__device__ float         g_hsel[BATCH * 128];        // selected-user h accumulators
__device__ int           g_map[NUM_USERS];           // user -> first batch slot
__device__ __nv_bfloat16 g_zb[BATCH * EMB];          // z in bf16
__device__ float         g_sexp[BATCH];
__device__ float         g_sdot[BATCH];
__device__ float         g_scnt[BATCH];
__device__ float         g_kl;

// ---- 0: zero scratch ----
__global__ void k_zero() {
    int i = blockIdx.x * blockDim.x + threadIdx.x;
    if (i < BATCH * 128) g_hsel[i] = 0.f;
    if (i < NUM_USERS)   g_map[i] = INTMX;
    if (i < BATCH) { g_sexp[i] = 0.f; g_sdot[i] = 0.f; g_scnt[i] = 0.f; }
    if (i == 0) g_kl = 0.f;
}

// ---- 1: build user -> slot map ----
__global__ void k_map(const int* __restrict__ user) {
    int b = blockIdx.x * blockDim.x + threadIdx.x;
    if (b < BATCH) atomicMin(&g_map[user[b]], b);
}

// ---- 2: transpose Wq[128][40000] -> WqT[40000][128] (tiled, coalesced both ways) ----
__global__ void k_transpose(const float* __restrict__ Wq) {
    __shared__ float tile[32][33];
    int i0 = blockIdx.x * 32, k0 = blockIdx.y * 32;
    int tx = threadIdx.x, ty = threadIdx.y;      // block (32,8)
#pragma unroll
    for (int r = 0; r < 32; r += 8)
        tile[ty + r][tx] = Wq[(size_t)(k0 + ty + r) * NUM_ITEMS + i0 + tx];
    __syncthreads();
#pragma unroll
    for (int r = 0; r < 32; r += 8)
        g_WqT[(size_t)(i0 + ty + r) * 128 + k0 + tx] = tile[tx][ty + r];
}

// ---- 3: Wp f32 -> bf16 ----
__global__ void k_wpcvt(const float* __restrict__ Wp) {
    int i = blockIdx.x * blockDim.x + threadIdx.x;
    if (i < NUM_ITEMS * EMB / 2) {
        float2 v = ((const float2*)Wp)[i];
        ((__nv_bfloat162*)g_Wpb)[i] = __floats2bfloat162_rn(v.x, v.y);
    }
}

// ---- 4: scatter kept edges (warp-ballot compaction, warp-cooperative 128-wide add) ----
__global__ void k_edges(const float* __restrict__ vals,
                        const int* __restrict__ rows,
                        const int* __restrict__ cols) {
    int idx  = blockIdx.x * blockDim.x + threadIdx.x;
    int lane = threadIdx.x & 31;
    int slot = INTMX, col = 0;
    float val = 0.f;
    if (idx < NNZ) {
        slot = g_map[rows[idx]];
        col  = cols[idx];
        val  = vals[idx];
    }
    unsigned m = __ballot_sync(0xFFFFFFFFu, slot != INTMX);
    while (m) {
        int j = __ffs(m) - 1; m &= m - 1;
        int   c = __shfl_sync(0xFFFFFFFFu, col, j);
        float v = __shfl_sync(0xFFFFFFFFu, val, j);
        int   s = __shfl_sync(0xFFFFFFFFu, slot, j);
        const float* wr = &g_WqT[(size_t)c * 128];
        float* hr = &g_hsel[s * 128];
#pragma unroll
        for (int k = lane; k < 128; k += 32)
            atomicAdd(&hr[k], v * wr[k]);
    }
}

// ---- 5: reparameterize + KL ----
__global__ void k_z(const float* __restrict__ bq,
                    const float* __restrict__ eps,
                    const int* __restrict__ user) {
    int b = blockIdx.x, k = threadIdx.x;   // 64 threads
    int u = user[b];
    int s = g_map[u];
    float mu = g_hsel[s * 128 + k]      + bq[k];
    float lv = g_hsel[s * 128 + 64 + k] + bq[64 + k];
    float z  = mu + eps[u * EMB + k] * __expf(0.5f * lv);
    g_zb[b * EMB + k] = __float2bfloat16(z);
    float t = 1.f + lv - mu * mu - __expf(lv);
#pragma unroll
    for (int o = 16; o > 0; o >>= 1) t += __shfl_down_sync(0xFFFFFFFFu, t, o);
    __shared__ float sm[2];
    if ((threadIdx.x & 31) == 0) sm[threadIdx.x >> 5] = t;
    __syncthreads();
    if (threadIdx.x == 0) atomicAdd(&g_kl, sm[0] + sm[1]);
}

// ---- 6: fused decoder GEMM (bf16 HMMA) + exp/x-dot/count accumulation ----
__device__ __forceinline__ void mma16816(float* d, const unsigned* a, const unsigned* b) {
    asm volatile(
        "mma.sync.aligned.m16n8k16.row.col.f32.bf16.bf16.f32 "
        "{%0,%1,%2,%3}, {%4,%5,%6,%7}, {%8,%9}, {%0,%1,%2,%3};\n"
        : "+f"(d[0]), "+f"(d[1]), "+f"(d[2]), "+f"(d[3])
        : "r"(a[0]), "r"(a[1]), "r"(a[2]), "r"(a[3]), "r"(b[0]), "r"(b[1]));
}

__global__ void __launch_bounds__(256, 1)
k_gemm(const float* __restrict__ bp, const float* __restrict__ x) {
    int w = threadIdx.x >> 5, lane = threadIdx.x & 31;
    int wm = w & 3, wn = w >> 2;                 // 4 warps along M, 2 along N
    int m_base = blockIdx.y * 128 + wm * 32;     // batch rows (always in-range)
    int n_base = blockIdx.x * 128 + wn * 64;     // item cols (tail-predicated)
    int g = lane >> 2, tg = lane & 3;

    // A fragments: z tile 32(M) x 64(K), fully register-resident
    unsigned a[2][4][4];
#pragma unroll
    for (int mf = 0; mf < 2; mf++) {
        int r0 = m_base + mf * 16 + g;
#pragma unroll
        for (int kf = 0; kf < 4; kf++) {
            int kb = kf * 16 + tg * 2;
            a[mf][kf][0] = *(const unsigned*)&g_zb[(r0)     * 64 + kb];
            a[mf][kf][1] = *(const unsigned*)&g_zb[(r0 + 8) * 64 + kb];
            a[mf][kf][2] = *(const unsigned*)&g_zb[(r0)     * 64 + kb + 8];
            a[mf][kf][3] = *(const unsigned*)&g_zb[(r0 + 8) * 64 + kb + 8];
        }
    }

    float sexp[4] = {0, 0, 0, 0}, sdot[4] = {0, 0, 0, 0}, scnt[4] = {0, 0, 0, 0};

#pragma unroll
    for (int nf = 0; nf < 8; nf++) {
        int i0 = n_base + nf * 8;
        int ib = i0 + g;                 // this thread's B item row
        unsigned bf[4][2];
        if (ib < NUM_ITEMS) {
#pragma unroll
            for (int kf = 0; kf < 4; kf++) {
                bf[kf][0] = *(const unsigned*)&g_Wpb[(size_t)ib * 64 + kf * 16 + tg * 2];
                bf[kf][1] = *(const unsigned*)&g_Wpb[(size_t)ib * 64 + kf * 16 + tg * 2 + 8];
            }
        } else {
#pragma unroll
            for (int kf = 0; kf < 4; kf++) { bf[kf][0] = 0u; bf[kf][1] = 0u; }
        }
        float d[2][4] = {{0, 0, 0, 0}, {0, 0, 0, 0}};
#pragma unroll
        for (int mf = 0; mf < 2; mf++)
#pragma unroll
            for (int kf = 0; kf < 4; kf++)
                mma16816(d[mf], a[mf][kf], bf[kf]);

        // epilogue for this 8-col stripe: thread owns cols (i0+tg*2, +1)
        int c0 = i0 + tg * 2;
        if (c0 < NUM_ITEMS) {
            float2 bpv = *(const float2*)&bp[c0];
#pragma unroll
            for (int mf = 0; mf < 2; mf++)
#pragma unroll
                for (int h = 0; h < 2; h++) {
                    int row = m_base + mf * 16 + h * 8 + g;
                    float v0 = d[mf][h * 2 + 0] + bpv.x;
                    float v1 = d[mf][h * 2 + 1] + bpv.y;
                    float e0 = __expf(v0), e1 = __expf(v1);
                    float2 xv = *(const float2*)&x[(size_t)row * NUM_ITEMS + c0];
                    int li = mf * 2 + h;
                    sexp[li] += e0 + e1;
                    sdot[li] += xv.x * v0 + xv.y * v1;
                    scnt[li] += xv.x + xv.y;
                }
        }
    }

    // reduce across the 4 threads of each group (tg), then atomics per row
#pragma unroll
    for (int li = 0; li < 4; li++) {
        float se = sexp[li], sd = sdot[li], sc = scnt[li];
#pragma unroll
        for (int o = 1; o < 4; o <<= 1) {
            se += __shfl_xor_sync(0xFFFFFFFFu, se, o);
            sd += __shfl_xor_sync(0xFFFFFFFFu, sd, o);
            sc += __shfl_xor_sync(0xFFFFFFFFu, sc, o);
        }
        if (tg == 0) {
            int row = m_base + (li >> 1) * 16 + (li & 1) * 8 + g;
            atomicAdd(&g_sexp[row], se);
            atomicAdd(&g_sdot[row], sd);
            atomicAdd(&g_scnt[row], sc);
        }
    }
}

// ---- 7: final reduction ----
__global__ void k_final(float* __restrict__ out) {
    __shared__ float sm[256];
    float acc = 0.f;
    for (int r = threadIdx.x; r < BATCH; r += 256)
        acc += g_scnt[r] * logf(g_sexp[r]) - g_sdot[r];
    sm[threadIdx.x] = acc;
    __syncthreads();
    for (int o = 128; o > 0; o >>= 1) {
        if (threadIdx.x < o) sm[threadIdx.x] += sm[threadIdx.x + o];
        __syncthreads();
    }
    if (threadIdx.x == 0) {
        out[0] = sm[0] / (float)BATCH;
        out[1] = -0.5f * g_kl / (float)BATCH;
    }
}

extern "C" void kernel_launch(void* const* d_in, const int* in_sizes, int n_in,
                              void* d_out, int out_size) {
    const float* graph_vals = (const float*)d_in[0];
    const float* Wq         = (const float*)d_in[1];
    const float* bq         = (const float*)d_in[2];
    const float* Wp         = (const float*)d_in[3];
    const float* bp         = (const float*)d_in[4];
    const float* x          = (const float*)d_in[5];
    const float* eps        = (const float*)d_in[6];
    const int*   graph_rows = (const int*)d_in[7];
    const int*   graph_cols = (const int*)d_in[8];
    const int*   user       = (const int*)d_in[9];
    float* out = (float*)d_out;

    k_zero<<<512, 256>>>();
    k_map<<<4, 256>>>(user);
    {
        dim3 grid(NUM_ITEMS / 32, 128 / 32);
        dim3 blk(32, 8);
        k_transpose<<<grid, blk>>>(Wq);
    }
    k_wpcvt<<<(NUM_ITEMS * EMB / 2 + 255) / 256, 256>>>(Wp);
    k_edges<<<(NNZ + 255) / 256, 256>>>(graph_vals, graph_rows, graph_cols);
    k_z<<<BATCH, 64>>>(bq, eps, user);
    {
        dim3 grid((NUM_ITEMS + 127) / 128, BATCH / 128);
        k_gemm<<<grid, 256>>>(bp, x);
    }
    k_final<<<1, 256>>>(out);
}